// round 11
// baseline (speedup 1.0000x reference)
#include <cuda_runtime.h>
#include <cstdint>

#define B_DIM 2048
#define I_DIM 512
#define O_DIM 512
#define ODUP  (O_DIM * 2)       // duplicated-A/B row length in floats

#define BM 64
#define BN 64
#define BK 16
#define NTH 128
#define KSPLIT 2
#define KLEN (I_DIM / KSPLIT)   // 256
#define ASTRIDE 132             // 128 floats payload + 16B pad; 16B-aligned rows

// Scratch: A,B pre-duplicated ({a,a} pairs); partial-product buffer
__device__ float g_Ad[I_DIM * ODUP];
__device__ float g_Bd[I_DIM * ODUP];
__device__ float g_P[B_DIM * O_DIM];

// ---------- packed f32x2 helpers ----------
__device__ __forceinline__ unsigned long long pack2(float lo, float hi) {
    unsigned long long r;
    asm("mov.b64 %0, {%1, %2};" : "=l"(r) : "f"(lo), "f"(hi));
    return r;
}
__device__ __forceinline__ void unpack2(unsigned long long v, float& lo, float& hi) {
    asm("mov.b64 {%0, %1}, %2;" : "=f"(lo), "=f"(hi) : "l"(v));
}
__device__ __forceinline__ unsigned long long fma2(unsigned long long a, unsigned long long b,
                                                   unsigned long long c) {
    unsigned long long d;
    asm("fma.rn.f32x2 %0, %1, %2, %3;" : "=l"(d) : "l"(a), "l"(b), "l"(c));
    return d;
}
__device__ __forceinline__ unsigned long long mul2(unsigned long long a, unsigned long long b) {
    unsigned long long d;
    asm("mul.rn.f32x2 %0, %1, %2;" : "=l"(d) : "l"(a), "l"(b));
    return d;
}

// ---------- cp.async helpers ----------
__device__ __forceinline__ void cp_async16(uint32_t smem_addr, const void* gptr) {
    asm volatile("cp.async.cg.shared.global [%0], [%1], 16;" :: "r"(smem_addr), "l"(gptr));
}
__device__ __forceinline__ void cp_commit() { asm volatile("cp.async.commit_group;"); }
__device__ __forceinline__ void cp_wait0()  { asm volatile("cp.async.wait_group 0;"); }

// ---------- prep: sigmoid + refactor + DUPLICATED store ----------
// thread i handles source float2 i -> writes float4 {a0,a0,a1,a1} at same index.
__global__ void prep_kernel(const float* __restrict__ wl, const float* __restrict__ sl) {
    int i = blockIdx.x * blockDim.x + threadIdx.x;   // float2 index, 0..131071
    float2 w2 = ((const float2*)wl)[i];
    float2 s2 = ((const float2*)sl)[i];
    float w0 = 1.0f / (1.0f + __expf(-w2.x));
    float s0 = 1.0f / (1.0f + __expf(-s2.x));
    float w1 = 1.0f / (1.0f + __expf(-w2.y));
    float s1 = 1.0f / (1.0f + __expf(-s2.y));
    float a0 = 1.0f - w0 * s0, b0 = w0 * (2.0f * s0 - 1.0f);
    float a1 = 1.0f - w1 * s1, b1 = w1 * (2.0f * s1 - 1.0f);
    ((float4*)g_Ad)[i] = make_float4(a0, a0, a1, a1);
    ((float4*)g_Bd)[i] = make_float4(b0, b0, b1, b1);
}

// ---------- combine: OUT *= g_P ----------
__global__ void combine_kernel(float* __restrict__ OUT) {
    int i = blockIdx.x * blockDim.x + threadIdx.x;
    float4 o = ((const float4*)OUT)[i];
    float4 p = ((const float4*)g_P)[i];
    o.x *= p.x; o.y *= p.y; o.z *= p.z; o.w *= p.w;
    ((float4*)OUT)[i] = o;
}

// ---------- main: product-GEMM, 64x64 tile, 16x2 microtile, dup'd A/B ----------
__global__ __launch_bounds__(NTH, 4)
void fuzzy_prod_kernel(const float* __restrict__ X, float* __restrict__ OUT) {
    __shared__ __align__(16) float Xs[2][BK][BM];
    __shared__ __align__(16) float As[2][BK * ASTRIDE];
    __shared__ __align__(16) float Bs[2][BK * ASTRIDE];

    const int tid = threadIdx.x;
    const int tx  = tid & 31;      // o-pair: o = 2tx, 2tx+1
    const int ty  = tid >> 5;      // b-group: rows ty*16 .. ty*16+15
    const int bn0 = blockIdx.x * BN;
    const int bm0 = blockIdx.y * BM;
    const int k0  = blockIdx.z * KLEN;
    float* dst = (blockIdx.z == 0) ? OUT : g_P;

    // X loader: 64 rows x 16 k -> 8 floats (2 float4) per thread
    const int xrow = tid >> 1;           // 0..63
    const int xk8  = (tid & 1) * 8;      // 0 or 8
    // A/B cp.async loader: 16 rows x 128 floats (dup'd) = 512 chunks; 4 chunks/thread
    const int arow = tid >> 3;           // 0..15
    const int acol = (tid & 7) * 16;     // float offset, 4 consecutive 16B chunks

    const float* gA = &g_Ad[(k0 + arow) * ODUP + bn0 * 2 + acol];
    const float* gB = &g_Bd[(k0 + arow) * ODUP + bn0 * 2 + acol];
    const uint32_t sA = (uint32_t)__cvta_generic_to_shared(&As[0][arow * ASTRIDE + acol]);
    const uint32_t sB = (uint32_t)__cvta_generic_to_shared(&Bs[0][arow * ASTRIDE + acol]);
    const uint32_t bufBytesAB = (uint32_t)(BK * ASTRIDE * sizeof(float));

    const unsigned long long ONE2 = pack2(1.0f, 1.0f);
    unsigned long long acc[8][2];
#pragma unroll
    for (int p = 0; p < 8; p++) { acc[p][0] = ONE2; acc[p][1] = ONE2; }

    // ---- prologue: fill buffer 0 ----
    {
#pragma unroll
        for (int j = 0; j < 4; j++) {
            cp_async16(sA + j * 16, gA + j * 4);
            cp_async16(sB + j * 16, gB + j * 4);
        }
        cp_commit();
        float4 x0 = *(const float4*)&X[(bm0 + xrow) * I_DIM + k0 + xk8];
        float4 x1 = *(const float4*)&X[(bm0 + xrow) * I_DIM + k0 + xk8 + 4];
        float xv[8] = {x0.x, x0.y, x0.z, x0.w, x1.x, x1.y, x1.z, x1.w};
#pragma unroll
        for (int j = 0; j < 8; j++) {
            int k = xk8 + j;
            Xs[0][k][xrow ^ (8 * ((k >> 2) & 3))] = xv[j];
        }
        cp_wait0();
    }
    __syncthreads();

    int buf = 0;
    for (int kt = k0; kt < k0 + KLEN; kt += BK) {
        const int nxt = buf ^ 1;
        const bool has_next = (kt + BK < k0 + KLEN);
        const int koff = kt - k0 + BK;
        float4 xn0, xn1;
        if (has_next) {
            const uint32_t soff = (nxt ? bufBytesAB : 0);
#pragma unroll
            for (int j = 0; j < 4; j++) {
                cp_async16(sA + soff + j * 16, gA + koff * ODUP + j * 4);
                cp_async16(sB + soff + j * 16, gB + koff * ODUP + j * 4);
            }
            cp_commit();
            xn0 = *(const float4*)&X[(bm0 + xrow) * I_DIM + (kt + BK) + xk8];
            xn1 = *(const float4*)&X[(bm0 + xrow) * I_DIM + (kt + BK) + xk8 + 4];
        }

#pragma unroll
        for (int k = 0; k < BK; k++) {
            const int sw = 8 * ((k >> 2) & 3);
            // dup'd quads: one LDS.128 each, packs are free register-pair names
            float4 aq = *(const float4*)&As[buf][k * ASTRIDE + tx * 4];
            float4 bq = *(const float4*)&Bs[buf][k * ASTRIDE + tx * 4];
            unsigned long long a0d = pack2(aq.x, aq.y);
            unsigned long long a1d = pack2(aq.z, aq.w);
            unsigned long long b0d = pack2(bq.x, bq.y);
            unsigned long long b1d = pack2(bq.z, bq.w);
#pragma unroll
            for (int j = 0; j < 4; j++) {
                // warp-broadcast float4 (all lanes same address)
                float4 xv = *(const float4*)&Xs[buf][k][(ty * 16 + 4 * j) ^ sw];
                unsigned long long xp0 = pack2(xv.x, xv.y);
                unsigned long long xp1 = pack2(xv.z, xv.w);
                acc[2 * j][0]     = mul2(acc[2 * j][0],     fma2(xp0, b0d, a0d));
                acc[2 * j][1]     = mul2(acc[2 * j][1],     fma2(xp0, b1d, a1d));
                acc[2 * j + 1][0] = mul2(acc[2 * j + 1][0], fma2(xp1, b0d, a0d));
                acc[2 * j + 1][1] = mul2(acc[2 * j + 1][1], fma2(xp1, b1d, a1d));
            }
        }

        if (has_next) {
            float xv[8] = {xn0.x, xn0.y, xn0.z, xn0.w, xn1.x, xn1.y, xn1.z, xn1.w};
#pragma unroll
            for (int j = 0; j < 8; j++) {
                int k = xk8 + j;
                Xs[nxt][k][xrow ^ (8 * ((k >> 2) & 3))] = xv[j];
            }
            cp_wait0();
        }
        __syncthreads();
        buf = nxt;
    }

    // ---- epilogue: 16 coalesced STG.64 per thread ----
#pragma unroll
    for (int p = 0; p < 8; p++) {
        float e0, e1, f0, f1;
        unpack2(acc[p][0], e0, e1);   // col 2tx,   rows 2p, 2p+1
        unpack2(acc[p][1], f0, f1);   // col 2tx+1
        const int row = bm0 + ty * 16 + 2 * p;
        *(float2*)&dst[row * O_DIM + bn0 + tx * 2]       = make_float2(e0, f0);
        *(float2*)&dst[(row + 1) * O_DIM + bn0 + tx * 2] = make_float2(e1, f1);
    }
}

extern "C" void kernel_launch(void* const* d_in, const int* in_sizes, int n_in,
                              void* d_out, int out_size) {
    const float* x  = (const float*)d_in[0];   // (2048, 512)
    const float* wl = (const float*)d_in[1];   // (512, 512)
    const float* sl = (const float*)d_in[2];   // (512, 512)
    float* out = (float*)d_out;                // (2048, 512)

    prep_kernel<<<(I_DIM * O_DIM / 2) / 256, 256>>>(wl, sl);   // 512 CTAs, 4096 warps

    dim3 grid(O_DIM / BN, B_DIM / BM, KSPLIT);  // (8, 32, 2) = 512 CTAs
    fuzzy_prod_kernel<<<grid, NTH>>>(x, out);

    combine_kernel<<<(B_DIM * O_DIM / 4) / 256, 256>>>(out);
}

// round 14
// speedup vs baseline: 1.2161x; 1.2161x over previous
#include <cuda_runtime.h>
#include <cstdint>

#define B_DIM 2048
#define I_DIM 512
#define O_DIM 512

#define BM 64
#define BN 32
#define BK 16
#define NTH 64
#define ASTRIDE 36   // 32 payload + 4 pad floats; rows 16B-aligned

// Scratch: precomputed A = 1 - w*s, B = w*(2s-1)
__device__ float g_A[I_DIM * O_DIM];
__device__ float g_B[I_DIM * O_DIM];

// ---------- packed f32x2 helpers ----------
__device__ __forceinline__ unsigned long long pack2(float lo, float hi) {
    unsigned long long r;
    asm("mov.b64 %0, {%1, %2};" : "=l"(r) : "f"(lo), "f"(hi));
    return r;
}
__device__ __forceinline__ void unpack2(unsigned long long v, float& lo, float& hi) {
    asm("mov.b64 {%0, %1}, %2;" : "=f"(lo), "=f"(hi) : "l"(v));
}
__device__ __forceinline__ unsigned long long fma2(unsigned long long a, unsigned long long b,
                                                   unsigned long long c) {
    unsigned long long d;
    asm("fma.rn.f32x2 %0, %1, %2, %3;" : "=l"(d) : "l"(a), "l"(b), "l"(c));
    return d;
}
__device__ __forceinline__ unsigned long long mul2(unsigned long long a, unsigned long long b) {
    unsigned long long d;
    asm("mul.rn.f32x2 %0, %1, %2;" : "=l"(d) : "l"(a), "l"(b));
    return d;
}

// ---------- cp.async helpers ----------
__device__ __forceinline__ void cp_async16(uint32_t smem_addr, const void* gptr) {
    asm volatile("cp.async.cg.shared.global [%0], [%1], 16;" :: "r"(smem_addr), "l"(gptr));
}
__device__ __forceinline__ void cp_commit() { asm volatile("cp.async.commit_group;"); }
__device__ __forceinline__ void cp_wait0()  { asm volatile("cp.async.wait_group 0;"); }

// ---------- prep: scalar (empirically the fastest prep variant) ----------
__global__ void prep_kernel(const float* __restrict__ wl, const float* __restrict__ sl) {
    int idx = blockIdx.x * blockDim.x + threadIdx.x;
    float w = 1.0f / (1.0f + __expf(-wl[idx]));
    float s = 1.0f / (1.0f + __expf(-sl[idx]));
    g_A[idx] = 1.0f - w * s;          // factor = A + x*B
    g_B[idx] = w * (2.0f * s - 1.0f);
}

// ---------- main: mono product-GEMM, 64x32 tile, 16x2 microtile, 64 threads ----------
__global__ __launch_bounds__(NTH, 6)
void fuzzy_prod_kernel(const float* __restrict__ X, float* __restrict__ OUT) {
    __shared__ __align__(16) float Xs[2][BK][BM];        // 8 KB
    __shared__ __align__(16) float As[2][BK * ASTRIDE];  // 4.6 KB
    __shared__ __align__(16) float Bs[2][BK * ASTRIDE];  // 4.6 KB

    const int tid = threadIdx.x;
    const int tx  = tid & 15;      // o-pair: o = 2tx, 2tx+1  (BN=32)
    const int ty  = tid >> 4;      // b-group: rows ty*16 .. ty*16+15 (4 groups)
    const int bn0 = blockIdx.x * BN;
    const int bm0 = blockIdx.y * BM;

    // X loader: each thread owns one b-row (tid), 16 k per tile (4 float4 LDG)
    const float* gX = &X[(bm0 + tid) * I_DIM];
    // A/B loader: tile 16 rows x 32 floats = 128 x 16B chunks; 2 chunks/thread/array
    //   chunk c in {tid, tid+64}: row = c>>3, col = (c&7)*4
    const int r0 = tid >> 3, c0 = (tid & 7) * 4;   // chunk tid
    const int r1 = r0 + 8;                          // chunk tid+64
    const float* gA0 = &g_A[r0 * O_DIM + bn0 + c0];
    const float* gA1 = &g_A[r1 * O_DIM + bn0 + c0];
    const float* gB0 = &g_B[r0 * O_DIM + bn0 + c0];
    const float* gB1 = &g_B[r1 * O_DIM + bn0 + c0];
    const uint32_t sA0 = (uint32_t)__cvta_generic_to_shared(&As[0][r0 * ASTRIDE + c0]);
    const uint32_t sA1 = (uint32_t)__cvta_generic_to_shared(&As[0][r1 * ASTRIDE + c0]);
    const uint32_t sB0 = (uint32_t)__cvta_generic_to_shared(&Bs[0][r0 * ASTRIDE + c0]);
    const uint32_t sB1 = (uint32_t)__cvta_generic_to_shared(&Bs[0][r1 * ASTRIDE + c0]);
    const uint32_t bufBytesAB = (uint32_t)(BK * ASTRIDE * sizeof(float));

    const unsigned long long ONE2 = pack2(1.0f, 1.0f);
    unsigned long long acc[8][2];
#pragma unroll
    for (int p = 0; p < 8; p++) { acc[p][0] = ONE2; acc[p][1] = ONE2; }

    // ---- prologue: fill buffer 0 ----
    {
        cp_async16(sA0, gA0);
        cp_async16(sA1, gA1);
        cp_async16(sB0, gB0);
        cp_async16(sB1, gB1);
        cp_commit();
        float4 xq[4];
#pragma unroll
        for (int c = 0; c < 4; c++) xq[c] = *(const float4*)&gX[c * 4];
        // transpose store: per-k STS, lanes = consecutive b -> conflict-free, no swizzle
#pragma unroll
        for (int c = 0; c < 4; c++) {
            Xs[0][c * 4 + 0][tid] = xq[c].x;
            Xs[0][c * 4 + 1][tid] = xq[c].y;
            Xs[0][c * 4 + 2][tid] = xq[c].z;
            Xs[0][c * 4 + 3][tid] = xq[c].w;
        }
        cp_wait0();
    }
    __syncthreads();

    int buf = 0;
    for (int kt = 0; kt < I_DIM; kt += BK) {
        const int nxt = buf ^ 1;
        const bool has_next = (kt + BK < I_DIM);
        float4 xq[4];
        if (has_next) {
            const uint32_t soff = (nxt ? bufBytesAB : 0);
            const int koff = kt + BK;
            cp_async16(sA0 + soff, gA0 + koff * O_DIM);
            cp_async16(sA1 + soff, gA1 + koff * O_DIM);
            cp_async16(sB0 + soff, gB0 + koff * O_DIM);
            cp_async16(sB1 + soff, gB1 + koff * O_DIM);
            cp_commit();
#pragma unroll
            for (int c = 0; c < 4; c++) xq[c] = *(const float4*)&gX[koff + c * 4];
        }

#pragma unroll
        for (int k = 0; k < BK; k++) {
            float2 av = *(const float2*)&As[buf][k * ASTRIDE + tx * 2];
            float2 bv = *(const float2*)&Bs[buf][k * ASTRIDE + tx * 2];
            unsigned long long a0d = pack2(av.x, av.x);
            unsigned long long a1d = pack2(av.y, av.y);
            unsigned long long b0d = pack2(bv.x, bv.x);
            unsigned long long b1d = pack2(bv.y, bv.y);
#pragma unroll
            for (int j = 0; j < 4; j++) {
                // broadcast read: only 2 distinct addresses per warp
                float4 xv = *(const float4*)&Xs[buf][k][ty * 16 + 4 * j];
                unsigned long long xp0 = pack2(xv.x, xv.y);
                unsigned long long xp1 = pack2(xv.z, xv.w);
                acc[2 * j][0]     = mul2(acc[2 * j][0],     fma2(xp0, b0d, a0d));
                acc[2 * j][1]     = mul2(acc[2 * j][1],     fma2(xp0, b1d, a1d));
                acc[2 * j + 1][0] = mul2(acc[2 * j + 1][0], fma2(xp1, b0d, a0d));
                acc[2 * j + 1][1] = mul2(acc[2 * j + 1][1], fma2(xp1, b1d, a1d));
            }
        }

        if (has_next) {
#pragma unroll
            for (int c = 0; c < 4; c++) {
                Xs[nxt][c * 4 + 0][tid] = xq[c].x;
                Xs[nxt][c * 4 + 1][tid] = xq[c].y;
                Xs[nxt][c * 4 + 2][tid] = xq[c].z;
                Xs[nxt][c * 4 + 3][tid] = xq[c].w;
            }
            cp_wait0();
        }
        __syncthreads();
        buf = nxt;
    }

    // ---- epilogue: 16 coalesced STG.64 per thread ----
#pragma unroll
    for (int p = 0; p < 8; p++) {
        float e0, e1, f0, f1;
        unpack2(acc[p][0], e0, e1);   // col 2tx,   rows 2p, 2p+1
        unpack2(acc[p][1], f0, f1);   // col 2tx+1
        const int row = bm0 + ty * 16 + 2 * p;
        *(float2*)&OUT[row * O_DIM + bn0 + tx * 2]       = make_float2(e0, f0);
        *(float2*)&OUT[(row + 1) * O_DIM + bn0 + tx * 2] = make_float2(e1, f1);
    }
}

extern "C" void kernel_launch(void* const* d_in, const int* in_sizes, int n_in,
                              void* d_out, int out_size) {
    const float* x  = (const float*)d_in[0];   // (2048, 512)
    const float* wl = (const float*)d_in[1];   // (512, 512)
    const float* sl = (const float*)d_in[2];   // (512, 512)
    float* out = (float*)d_out;                // (2048, 512)

    prep_kernel<<<(I_DIM * O_DIM) / 256, 256>>>(wl, sl);

    dim3 grid(O_DIM / BN, B_DIM / BM);  // (16, 32) = 512 CTAs, mono-kernel
    fuzzy_prod_kernel<<<grid, NTH>>>(x, out);
}

// round 15
// speedup vs baseline: 1.2471x; 1.0255x over previous
#include <cuda_runtime.h>
#include <cstdint>

#define B_DIM 2048
#define I_DIM 512
#define O_DIM 512

#define BM 32
#define BN 32
#define BK 16
#define NTH 64
#define ASTRIDE 36   // 32 payload + 4 pad floats; rows 16B-aligned

// Scratch: precomputed A = 1 - w*s, B = w*(2s-1)
__device__ float g_A[I_DIM * O_DIM];
__device__ float g_B[I_DIM * O_DIM];

// ---------- packed f32x2 helpers ----------
__device__ __forceinline__ unsigned long long pack2(float lo, float hi) {
    unsigned long long r;
    asm("mov.b64 %0, {%1, %2};" : "=l"(r) : "f"(lo), "f"(hi));
    return r;
}
__device__ __forceinline__ void unpack2(unsigned long long v, float& lo, float& hi) {
    asm("mov.b64 {%0, %1}, %2;" : "=f"(lo), "=f"(hi) : "l"(v));
}
__device__ __forceinline__ unsigned long long fma2(unsigned long long a, unsigned long long b,
                                                   unsigned long long c) {
    unsigned long long d;
    asm("fma.rn.f32x2 %0, %1, %2, %3;" : "=l"(d) : "l"(a), "l"(b), "l"(c));
    return d;
}
__device__ __forceinline__ unsigned long long mul2(unsigned long long a, unsigned long long b) {
    unsigned long long d;
    asm("mul.rn.f32x2 %0, %1, %2;" : "=l"(d) : "l"(a), "l"(b));
    return d;
}

// ---------- cp.async helpers ----------
__device__ __forceinline__ void cp_async16(uint32_t smem_addr, const void* gptr) {
    asm volatile("cp.async.cg.shared.global [%0], [%1], 16;" :: "r"(smem_addr), "l"(gptr));
}
__device__ __forceinline__ void cp_commit() { asm volatile("cp.async.commit_group;"); }
__device__ __forceinline__ void cp_wait0()  { asm volatile("cp.async.wait_group 0;"); }

// ---------- prep: scalar (empirically fastest) ----------
__global__ void prep_kernel(const float* __restrict__ wl, const float* __restrict__ sl) {
    int idx = blockIdx.x * blockDim.x + threadIdx.x;
    float w = 1.0f / (1.0f + __expf(-wl[idx]));
    float s = 1.0f / (1.0f + __expf(-sl[idx]));
    g_A[idx] = 1.0f - w * s;          // factor = A + x*B
    g_B[idx] = w * (2.0f * s - 1.0f);
}

// ---------- main: mono product-GEMM, 32x32 tile, 8x2 microtile, 1024 CTAs ----------
__global__ __launch_bounds__(NTH, 8)
void fuzzy_prod_kernel(const float* __restrict__ X, float* __restrict__ OUT) {
    __shared__ __align__(16) float Xs[2][BK][BM];        // 4 KB
    __shared__ __align__(16) float As[2][BK * ASTRIDE];  // 4.6 KB
    __shared__ __align__(16) float Bs[2][BK * ASTRIDE];  // 4.6 KB

    const int tid = threadIdx.x;
    const int tx  = tid & 15;      // o-pair: o = 2tx, 2tx+1   (BN=32)
    const int ty  = tid >> 4;      // b-group: rows ty*8 .. ty*8+7 (4 groups)
    const int bn0 = blockIdx.x * BN;
    const int bm0 = blockIdx.y * BM;

    // X loader: 32 rows x 16 k; thread loads row (tid&31), k-offset 8*(tid>>5) -> 2 float4
    const int xrow = tid & 31;
    const int xk8  = (tid >> 5) * 8;
    const float* gX = &X[(bm0 + xrow) * I_DIM + xk8];
    // A/B loader: tile 16 rows x 32 floats = 128 x 16B chunks; 2 chunks/thread/array
    const int r0 = tid >> 3, c0 = (tid & 7) * 4;   // rows 0..7
    const int r1 = r0 + 8;                          // rows 8..15
    const float* gA0 = &g_A[r0 * O_DIM + bn0 + c0];
    const float* gA1 = &g_A[r1 * O_DIM + bn0 + c0];
    const float* gB0 = &g_B[r0 * O_DIM + bn0 + c0];
    const float* gB1 = &g_B[r1 * O_DIM + bn0 + c0];
    const uint32_t sA0 = (uint32_t)__cvta_generic_to_shared(&As[0][r0 * ASTRIDE + c0]);
    const uint32_t sA1 = (uint32_t)__cvta_generic_to_shared(&As[0][r1 * ASTRIDE + c0]);
    const uint32_t sB0 = (uint32_t)__cvta_generic_to_shared(&Bs[0][r0 * ASTRIDE + c0]);
    const uint32_t sB1 = (uint32_t)__cvta_generic_to_shared(&Bs[0][r1 * ASTRIDE + c0]);
    const uint32_t bufBytesAB = (uint32_t)(BK * ASTRIDE * sizeof(float));

    const unsigned long long ONE2 = pack2(1.0f, 1.0f);
    // acc[p][o]: packed b-pair (ty*8+2p, ty*8+2p+1), o column 2tx+o
    unsigned long long acc[4][2];
#pragma unroll
    for (int p = 0; p < 4; p++) { acc[p][0] = ONE2; acc[p][1] = ONE2; }

    // ---- prologue: fill buffer 0 ----
    {
        cp_async16(sA0, gA0);
        cp_async16(sA1, gA1);
        cp_async16(sB0, gB0);
        cp_async16(sB1, gB1);
        cp_commit();
        float4 x0 = *(const float4*)&gX[0];
        float4 x1 = *(const float4*)&gX[4];
        float xv[8] = {x0.x, x0.y, x0.z, x0.w, x1.x, x1.y, x1.z, x1.w};
#pragma unroll
        for (int j = 0; j < 8; j++) Xs[0][xk8 + j][xrow] = xv[j];
        cp_wait0();
    }
    __syncthreads();

    int buf = 0;
    for (int kt = 0; kt < I_DIM; kt += BK) {
        const int nxt = buf ^ 1;
        const bool has_next = (kt + BK < I_DIM);
        float4 x0, x1;
        if (has_next) {
            const uint32_t soff = (nxt ? bufBytesAB : 0);
            const int koff = kt + BK;
            cp_async16(sA0 + soff, gA0 + koff * O_DIM);
            cp_async16(sA1 + soff, gA1 + koff * O_DIM);
            cp_async16(sB0 + soff, gB0 + koff * O_DIM);
            cp_async16(sB1 + soff, gB1 + koff * O_DIM);
            cp_commit();
            x0 = *(const float4*)&gX[koff];
            x1 = *(const float4*)&gX[koff + 4];
        }

#pragma unroll
        for (int k = 0; k < BK; k++) {
            // A/B: 16 distinct LDS.64 per warp -> conflict-free, dedup'd (1 wf each)
            float2 av = *(const float2*)&As[buf][k * ASTRIDE + tx * 2];
            float2 bv = *(const float2*)&Bs[buf][k * ASTRIDE + tx * 2];
            unsigned long long a0d = pack2(av.x, av.x);
            unsigned long long a1d = pack2(av.y, av.y);
            unsigned long long b0d = pack2(bv.x, bv.x);
            unsigned long long b1d = pack2(bv.y, bv.y);
            // X: 2 distinct float4 per warp, same 128B row -> 1 wf each
            float4 xv0 = *(const float4*)&Xs[buf][k][ty * 8];
            float4 xv1 = *(const float4*)&Xs[buf][k][ty * 8 + 4];
            unsigned long long xp0 = pack2(xv0.x, xv0.y);
            unsigned long long xp1 = pack2(xv0.z, xv0.w);
            unsigned long long xp2 = pack2(xv1.x, xv1.y);
            unsigned long long xp3 = pack2(xv1.z, xv1.w);

            acc[0][0] = mul2(acc[0][0], fma2(xp0, b0d, a0d));
            acc[0][1] = mul2(acc[0][1], fma2(xp0, b1d, a1d));
            acc[1][0] = mul2(acc[1][0], fma2(xp1, b0d, a0d));
            acc[1][1] = mul2(acc[1][1], fma2(xp1, b1d, a1d));
            acc[2][0] = mul2(acc[2][0], fma2(xp2, b0d, a0d));
            acc[2][1] = mul2(acc[2][1], fma2(xp2, b1d, a1d));
            acc[3][0] = mul2(acc[3][0], fma2(xp3, b0d, a0d));
            acc[3][1] = mul2(acc[3][1], fma2(xp3, b1d, a1d));
        }

        if (has_next) {
            float xv[8] = {x0.x, x0.y, x0.z, x0.w, x1.x, x1.y, x1.z, x1.w};
#pragma unroll
            for (int j = 0; j < 8; j++) Xs[nxt][xk8 + j][xrow] = xv[j];
            cp_wait0();
        }
        __syncthreads();
        buf = nxt;
    }

    // ---- epilogue: 8 coalesced STG.64 per thread ----
#pragma unroll
    for (int p = 0; p < 4; p++) {
        float e0, e1, f0, f1;
        unpack2(acc[p][0], e0, e1);   // col 2tx,   rows 2p, 2p+1
        unpack2(acc[p][1], f0, f1);   // col 2tx+1
        const int row = bm0 + ty * 8 + 2 * p;
        *(float2*)&OUT[row * O_DIM + bn0 + tx * 2]       = make_float2(e0, f0);
        *(float2*)&OUT[(row + 1) * O_DIM + bn0 + tx * 2] = make_float2(e1, f1);
    }
}

extern "C" void kernel_launch(void* const* d_in, const int* in_sizes, int n_in,
                              void* d_out, int out_size) {
    const float* x  = (const float*)d_in[0];   // (2048, 512)
    const float* wl = (const float*)d_in[1];   // (512, 512)
    const float* sl = (const float*)d_in[2];   // (512, 512)
    float* out = (float*)d_out;                // (2048, 512)

    prep_kernel<<<(I_DIM * O_DIM) / 256, 256>>>(wl, sl);

    dim3 grid(O_DIM / BN, B_DIM / BM);  // (16, 64) = 1024 CTAs, mono-kernel
    fuzzy_prod_kernel<<<grid, NTH>>>(x, out);
}